// round 1
// baseline (speedup 1.0000x reference)
#include <cuda_runtime.h>
#include <math_constants.h>

// EnhancedLIFNeuron: B=128, T=128, F=2048, KW=5
// inputs (metadata order): x[B*T*F] f32, init_threshold[1], conv_w[5], conv_b[1], spatial_attn[1]
// output: spikes[B,T,F] followed by mem[B,F], f32, total 33,816,576 elems.

#define TT    128
#define FF    2048
#define BB    128
#define BLOCK 64

__global__ __launch_bounds__(BLOCK)
void lif_fused_kernel(const float* __restrict__ x,
                      const float* __restrict__ thr_p,
                      const float* __restrict__ cw,
                      const float* __restrict__ cb,
                      const float* __restrict__ sa,
                      float* __restrict__ out)
{
    // Per-thread private column of conv values. No cross-thread sharing,
    // so no __syncthreads needed anywhere. 128*64*4 = 32 KB static smem.
    __shared__ float csm[TT * BLOCK];

    const int tid = threadIdx.x;
    const int g   = blockIdx.x * BLOCK + tid;     // lane id in [0, B*F)
    const int f   = g & (FF - 1);
    const int b   = g >> 11;                      // FF = 2^11

    const float* xp = x + b * (TT * FF) + f;      // stride FF between timesteps

    const float w0 = cw[0], w1 = cw[1], w2 = cw[2], w3 = cw[3], w4 = cw[4];
    const float bias = cb[0];
    const float thr0 = thr_p[0];
    const float satt = sa[0];

    // ---- streaming conv (cross-correlation, zero-padded SAME) + running sum ----
    float xm2 = 0.f, xm1 = 0.f;
    float x0  = xp[0];
    float xp1 = xp[FF];
    float sum = 0.f;

    #pragma unroll 8
    for (int t = 0; t < TT; ++t) {
        float xp2 = (t + 2 < TT) ? xp[(t + 2) * FF] : 0.f;
        float cv = fmaf(w0, xm2,
                   fmaf(w1, xm1,
                   fmaf(w2, x0,
                   fmaf(w3, xp1,
                   fmaf(w4, xp2, bias)))));
        csm[t * BLOCK + tid] = cv;
        sum += cv;
        xm2 = xm1; xm1 = x0; x0 = xp1; xp1 = xp2;
    }

    // ---- spatial attention scalar ----
    const float mean  = sum * (1.0f / (float)TT);
    const float watt  = 1.0f / (1.0f + expf(-satt * mean));
    const float scale = 1.0f + 0.5f * watt;       // GAMMA = 0.5

    // ---- LIF recurrence ----
    float mem = 0.f;
    float thr = thr0;
    float h1 = 0.f, h2 = 0.f;                     // 3-tap history (h0 implicit)

    float* sp = out + b * (TT * FF) + f;

    const float PI      = CUDART_PI_F;
    const float HALF_PI = 0.5f * CUDART_PI_F;
    const float INV2PI  = 0.5f / CUDART_PI_F;

    #pragma unroll 4
    for (int t = 0; t < TT; ++t) {
        float xt = csm[t * BLOCK + tid] * scale;
        mem = fmaf(0.9f, mem, xt);                            // DECAY
        float z     = (mem - thr) * HALF_PI;
        float spike = fmaf(atanf(z), INV2PI, 0.25f);          // multi_atan surrogate
        float avg   = (h1 + h2 + spike) * (1.0f / 3.0f);
        h1 = h2; h2 = spike;
        thr = fmaf(0.9f, thr, fmaf(0.1f, thr0, 0.1f * avg));  // ALPHA, BETA
        mem = fmaf(-spike, thr, mem);
        sp[t * FF] = spike;
    }

    // mem output appended after spikes
    out[BB * TT * FF + b * FF + f] = mem;
    (void)PI;
}

extern "C" void kernel_launch(void* const* d_in, const int* in_sizes, int n_in,
                              void* d_out, int out_size)
{
    const float* x    = (const float*)d_in[0];
    const float* thr0 = (const float*)d_in[1];
    const float* cw   = (const float*)d_in[2];
    const float* cb   = (const float*)d_in[3];
    const float* sa   = (const float*)d_in[4];
    float* out = (float*)d_out;

    const int lanes = BB * FF;              // 262144
    dim3 grid(lanes / BLOCK);               // 4096 blocks
    lif_fused_kernel<<<grid, BLOCK>>>(x, thr0, cw, cb, sa, out);
}

// round 2
// speedup vs baseline: 1.5398x; 1.5398x over previous
#include <cuda_runtime.h>
#include <math_constants.h>

// EnhancedLIFNeuron: B=128, T=128, F=2048, KW=5
// inputs: x[B*T*F] f32, init_threshold[1], conv_w[5], conv_b[1], spatial_attn[1]
// output: spikes[B,T,F] then mem[B,F], f32.

#define TT    128
#define FF    2048
#define BB    128
#define BLOCK 256

// Fast atan: degree-11 odd minimax on [0,1] + reciprocal range reduction.
// Max abs error ~2.3e-7 — far below the 1e-3 output tolerance.
__device__ __forceinline__ float fast_atan(float x)
{
    const float a1  =  0.99997726f;
    const float a3  = -0.33262347f;
    const float a5  =  0.19354346f;
    const float a7  = -0.11643287f;
    const float a9  =  0.05265332f;
    const float a11 = -0.01172120f;

    float ax  = fabsf(x);
    bool  big = ax > 1.0f;
    float t   = big ? __fdividef(1.0f, ax) : ax;   // MUFU.RCP path
    float t2  = t * t;
    float p   = fmaf(t2, a11, a9);
    p = fmaf(t2, p, a7);
    p = fmaf(t2, p, a5);
    p = fmaf(t2, p, a3);
    p = fmaf(t2, p, a1);
    float r = t * p;
    r = big ? (CUDART_PIO2_F - r) : r;
    return copysignf(r, x);
}

__global__ __launch_bounds__(BLOCK)
void lif_fused_kernel(const float* __restrict__ x,
                      const float* __restrict__ thr_p,
                      const float* __restrict__ cw,
                      const float* __restrict__ cb,
                      const float* __restrict__ sa,
                      float* __restrict__ out)
{
    const int g = blockIdx.x * BLOCK + threadIdx.x;   // lane in [0, B*F)
    const int f = g & (FF - 1);
    const int b = g >> 11;                            // FF = 2^11

    const float* __restrict__ xp = x + b * (TT * FF) + f;   // stride FF over t

    const float w0 = cw[0], w1 = cw[1], w2 = cw[2], w3 = cw[3], w4 = cw[4];
    const float bias = cb[0];
    const float thr0 = thr_p[0];
    const float satt = sa[0];

    // ---------- pass 1: plain sum of x over t (streaming, high MLP) ----------
    float s0 = 0.f, s1 = 0.f, s2 = 0.f, s3 = 0.f;
    #pragma unroll 8
    for (int t = 0; t < TT; t += 4) {
        s0 += xp[(t + 0) * FF];
        s1 += xp[(t + 1) * FF];
        s2 += xp[(t + 2) * FF];
        s3 += xp[(t + 3) * FF];
    }
    const float S = (s0 + s1) + (s2 + s3);

    const float xe0 = xp[0];
    const float xe1 = xp[FF];
    const float xT2 = xp[(TT - 2) * FF];
    const float xT1 = xp[(TT - 1) * FF];

    // sum_t conv[t] analytically (conv is linear; SAME zero padding edges):
    const float wsum = w0 + w1 + w2 + w3 + w4;
    float sum_conv = (float)TT * bias + wsum * S
                   - w0 * (xT2 + xT1) - w1 * xT1
                   - w3 * xe0 - w4 * (xe0 + xe1);

    const float mean  = sum_conv * (1.0f / (float)TT);
    const float watt  = 1.0f / (1.0f + expf(-satt * mean));
    const float scale = 1.0f + 0.5f * watt;          // GAMMA = 0.5

    // ---------- pass 2: fused conv + LIF recurrence, zero smem ----------
    float xm2 = 0.f, xm1 = 0.f;
    float x0  = xe0;
    float xp1 = xe1;

    float mem = 0.f;
    float thr = thr0;
    float h1 = 0.f, h2 = 0.f;                        // 3-tap spike history

    float* __restrict__ sp = out + b * (TT * FF) + f;

    const float HALF_PI = 0.5f * CUDART_PI_F;
    const float INV2PI  = 0.5f / CUDART_PI_F;

    #pragma unroll 4
    for (int t = 0; t < TT; ++t) {
        float xp2 = (t + 2 < TT) ? xp[(t + 2) * FF] : 0.f;

        float cv = fmaf(w0, xm2,
                   fmaf(w1, xm1,
                   fmaf(w2, x0,
                   fmaf(w3, xp1,
                   fmaf(w4, xp2, bias)))));
        float xt = cv * scale;

        mem = fmaf(0.9f, mem, xt);                               // DECAY
        float z     = (mem - thr) * HALF_PI;
        float spike = fmaf(fast_atan(z), INV2PI, 0.25f);         // surrogate
        float avg   = (h1 + h2 + spike) * (1.0f / 3.0f);
        h1 = h2; h2 = spike;
        thr = fmaf(0.9f, thr, fmaf(0.1f, thr0, 0.1f * avg));     // ALPHA/BETA
        mem = fmaf(-spike, thr, mem);

        sp[t * FF] = spike;

        xm2 = xm1; xm1 = x0; x0 = xp1; xp1 = xp2;
    }

    out[BB * TT * FF + g] = mem;   // g == b*FF + f
}

extern "C" void kernel_launch(void* const* d_in, const int* in_sizes, int n_in,
                              void* d_out, int out_size)
{
    const float* x    = (const float*)d_in[0];
    const float* thr0 = (const float*)d_in[1];
    const float* cw   = (const float*)d_in[2];
    const float* cb   = (const float*)d_in[3];
    const float* sa   = (const float*)d_in[4];
    float* out = (float*)d_out;

    const int lanes = BB * FF;                 // 262144
    lif_fused_kernel<<<lanes / BLOCK, BLOCK>>>(x, thr0, cw, cb, sa, out);
}

// round 4
// speedup vs baseline: 1.9194x; 1.2465x over previous
#include <cuda_runtime.h>
#include <math_constants.h>

// EnhancedLIFNeuron: B=128, T=128, F=2048, KW=5
// inputs: x[B*T*F] f32, init_threshold[1], conv_w[5], conv_b[1], spatial_attn[1]
// output: spikes[B,T,F] then mem[B,F], f32.

#define TT     128
#define FF     2048
#define FH     (FF/2)      // float2 stride per timestep = 1024
#define BB     128
#define BLOCK  256
#define CH     4           // prefetch chunk (timesteps)
#define NCHUNK (TT/CH)

__device__ __forceinline__ float fast_atan(float x)
{
    // degree-9 odd minimax on [-1,1] (|err| ~ 1e-5 rad), branchless range reduction
    float ax = fabsf(x);
    float rc = __fdividef(1.0f, ax);        // MUFU.RCP
    float t  = fminf(ax, rc);
    float t2 = t * t;
    float t4 = t2 * t2;
    float c0 = fmaf(t2, -0.3302995f, 0.9998660f);
    float c1 = fmaf(t2, -0.0851330f, 0.1801410f);
    float in = fmaf(t4,  0.0208351f, c1);
    float p  = fmaf(t4, in, c0);
    float r  = t * p;
    r = (ax > 1.0f) ? (CUDART_PIO2_F - r) : r;
    return copysignf(r, x);
}

__global__ __launch_bounds__(BLOCK, 4)
void lif_fused_kernel(const float* __restrict__ x,
                      const float* __restrict__ thr_p,
                      const float* __restrict__ cw,
                      const float* __restrict__ cb,
                      const float* __restrict__ sa,
                      float* __restrict__ out)
{
    const int p  = blockIdx.x * BLOCK + threadIdx.x;   // float2-lane id in [0, B*FH)
    const int fp = p & (FH - 1);
    const int b  = p >> 10;                            // FH = 2^10
    const int f  = fp * 2;

    const float2* __restrict__ xp =
        (const float2*)(x + (size_t)b * TT * FF + f);  // stride FH float2 per t

    const float w0 = cw[0], w1 = cw[1], w2 = cw[2], w3 = cw[3], w4 = cw[4];
    const float bias = cb[0];
    const float thr0 = thr_p[0];
    const float satt = sa[0];

    // ---------- pass 1: plain sum of x over t ----------
    float2 a0 = make_float2(0.f, 0.f), a1 = make_float2(0.f, 0.f);
    #pragma unroll 8
    for (int t = 0; t < TT; t += 2) {
        float2 u = xp[t * FH];
        float2 v = xp[(t + 1) * FH];
        a0.x += u.x; a0.y += u.y;
        a1.x += v.x; a1.y += v.y;
    }
    const float Sx = a0.x + a1.x;
    const float Sy = a0.y + a1.y;

    const float2 xe0 = xp[0];
    const float2 xe1 = xp[FH];
    const float2 xT2 = xp[(TT - 2) * FH];
    const float2 xT1 = xp[(TT - 1) * FH];

    // analytic sum of conv over t (linear conv, SAME zero padding):
    const float wsum = w0 + w1 + w2 + w3 + w4;
    const float cT = (float)TT * bias;
    float scx, scy;
    {
        float sc = cT + wsum * Sx
                 - w0 * (xT2.x + xT1.x) - w1 * xT1.x
                 - w3 * xe0.x - w4 * (xe0.x + xe1.x);
        float m  = sc * (1.0f / (float)TT);
        scx = 1.0f + 0.5f / (1.0f + expf(-satt * m));
    }
    {
        float sc = cT + wsum * Sy
                 - w0 * (xT2.y + xT1.y) - w1 * xT1.y
                 - w3 * xe0.y - w4 * (xe0.y + xe1.y);
        float m  = sc * (1.0f / (float)TT);
        scy = 1.0f + 0.5f / (1.0f + expf(-satt * m));
    }
    const float bx = bias * scx;     // folded bias*scale per lane
    const float by = bias * scy;

    // ---------- pass 2: fused conv + LIF with register prefetch pipeline ----------
    const float HALF_PI = 0.5f * CUDART_PI_F;
    const float INV2PI  = 0.5f / CUDART_PI_F;
    const float K3      = 0.1f / 3.0f;
    const float thr0c   = 0.1f * thr0;

    // conv window regs: x[t-2], x[t-1], x[t], x[t+1]
    float2 m2 = make_float2(0.f, 0.f), m1 = make_float2(0.f, 0.f);
    float2 c0v = xe0, p1v = xe1;

    // LIF state per lane
    float memx = 0.f, memy = 0.f;
    float thrx = thr0, thry = thr0;
    float thx  = thr0 * HALF_PI, thy = thr0 * HALF_PI;
    float h1x = 0.f, h2x = 0.f, h1y = 0.f, h2y = 0.f;

    float2 cur[CH], nxt[CH];
    #pragma unroll
    for (int i = 0; i < CH; ++i) cur[i] = xp[(2 + i) * FH];   // x[t+2] for t=0..CH-1

    float2* __restrict__ op = (float2*)(out + (size_t)b * TT * FF + f);

    #pragma unroll 1
    for (int c = 0; c < NCHUNK; ++c) {
        const int nbase = (c + 1) * CH + 2;
        #pragma unroll
        for (int i = 0; i < CH; ++i) {
            int idx = nbase + i;
            float2 v = make_float2(0.f, 0.f);
            if (idx < TT) v = xp[idx * FH];
            nxt[i] = v;
        }

        #pragma unroll
        for (int i = 0; i < CH; ++i) {
            float2 p2v = cur[i];

            // conv (no bias; bias*scale folded into bx/by)
            float cvx = fmaf(w1, m1.x, w0 * m2.x);
            cvx = fmaf(w2, c0v.x, cvx);
            cvx = fmaf(w3, p1v.x, cvx);
            cvx = fmaf(w4, p2v.x, cvx);
            float cvy = fmaf(w1, m1.y, w0 * m2.y);
            cvy = fmaf(w2, c0v.y, cvy);
            cvy = fmaf(w3, p1v.y, cvy);
            cvy = fmaf(w4, p2v.y, cvy);

            float xtx = fmaf(cvx, scx, bx);
            float xty = fmaf(cvy, scy, by);

            // LIF step lane x
            memx = fmaf(0.9f, memx, xtx);
            float zx  = fmaf(memx, HALF_PI, -thx);
            float spx = fmaf(fast_atan(zx), INV2PI, 0.25f);
            float prx = fmaf(0.9f, thrx, fmaf(K3, h1x + h2x, thr0c));
            thrx = fmaf(K3, spx, prx);
            thx  = thrx * HALF_PI;
            memx = fmaf(-spx, thrx, memx);
            h1x = h2x; h2x = spx;

            // LIF step lane y
            memy = fmaf(0.9f, memy, xty);
            float zy  = fmaf(memy, HALF_PI, -thy);
            float spy = fmaf(fast_atan(zy), INV2PI, 0.25f);
            float pry = fmaf(0.9f, thry, fmaf(K3, h1y + h2y, thr0c));
            thry = fmaf(K3, spy, pry);
            thy  = thry * HALF_PI;
            memy = fmaf(-spy, thry, memy);
            h1y = h2y; h2y = spy;

            __stcs(&op[(c * CH + i) * FH], make_float2(spx, spy));  // streaming store

            m2 = m1; m1 = c0v; c0v = p1v; p1v = p2v;
        }

        #pragma unroll
        for (int i = 0; i < CH; ++i) cur[i] = nxt[i];
    }

    // mem output appended after spikes (float2 aligned: f even)
    ((float2*)(out + (size_t)BB * TT * FF))[p] = make_float2(memx, memy);
}

extern "C" void kernel_launch(void* const* d_in, const int* in_sizes, int n_in,
                              void* d_out, int out_size)
{
    const float* x    = (const float*)d_in[0];
    const float* thr0 = (const float*)d_in[1];
    const float* cw   = (const float*)d_in[2];
    const float* cb   = (const float*)d_in[3];
    const float* sa   = (const float*)d_in[4];
    float* out = (float*)d_out;

    const int pairs = BB * FH;                 // 131072
    lif_fused_kernel<<<pairs / BLOCK, BLOCK>>>(x, thr0, cw, cb, sa, out);
}

// round 6
// speedup vs baseline: 2.0684x; 1.0776x over previous
#include <cuda_runtime.h>
#include <math_constants.h>

// EnhancedLIFNeuron: B=128, T=128, F=2048, KW=5
// inputs: x[B*T*F] f32, init_threshold[1], conv_w[5], conv_b[1], spatial_attn[1]
// output: spikes[B,T,F] then mem[B,F], f32.

#define TT     128
#define FF     2048
#define FH     (FF/2)      // float2 stride per timestep = 1024
#define BB     128
#define BLOCK  256

typedef unsigned long long ull;

// ---- packed f32x2 helpers (sm_103a FFMA2 path, PTX ISA 8.6) ----
__device__ __forceinline__ ull pk2(float l, float h) {
    ull r; asm("mov.b64 %0, {%1, %2};" : "=l"(r) : "f"(l), "f"(h)); return r;
}
__device__ __forceinline__ void up2(float& l, float& h, ull v) {
    asm("mov.b64 {%0, %1}, %2;" : "=f"(l), "=f"(h) : "l"(v));
}
__device__ __forceinline__ ull fma2(ull a, ull b, ull c) {
    ull d; asm("fma.rn.f32x2 %0, %1, %2, %3;" : "=l"(d) : "l"(a), "l"(b), "l"(c)); return d;
}
__device__ __forceinline__ ull mul2(ull a, ull b) {
    ull d; asm("mul.rn.f32x2 %0, %1, %2;" : "=l"(d) : "l"(a), "l"(b)); return d;
}
__device__ __forceinline__ ull add2(ull a, ull b) {
    ull d; asm("add.rn.f32x2 %0, %1, %2;" : "=l"(d) : "l"(a), "l"(b)); return d;
}
__device__ __forceinline__ ull sub2(ull a, ull b) {
    ull d; asm("sub.rn.f32x2 %0, %1, %2;" : "=l"(d) : "l"(a), "l"(b)); return d;
}

__global__ __launch_bounds__(BLOCK, 4)
void lif_fused_kernel(const float* __restrict__ x,
                      const float* __restrict__ thr_p,
                      const float* __restrict__ cw,
                      const float* __restrict__ cb,
                      const float* __restrict__ sa,
                      float* __restrict__ out)
{
    const int p  = blockIdx.x * BLOCK + threadIdx.x;   // float2-lane pair id
    const int fp = p & (FH - 1);
    const int b  = p >> 10;                            // FH = 2^10
    const int f  = fp * 2;

    const ull* __restrict__ xq = (const ull*)(x + (size_t)b * TT * FF + f);
    ull* __restrict__ oq       = (ull*)(out + (size_t)b * TT * FF + f);

    const float w0 = cw[0], w1 = cw[1], w2 = cw[2], w3 = cw[3], w4 = cw[4];
    const float bias = cb[0];
    const float thr0 = thr_p[0];
    const float satt = sa[0];

    // ---------- pass 1: sum x over t (packed adds, default caching -> L2) ----------
    ull s0 = 0ull, s1 = 0ull;
    #pragma unroll 8
    for (int t = 0; t < TT; t += 2) {
        s0 = add2(s0, xq[t * FH]);
        s1 = add2(s1, xq[(t + 1) * FH]);
    }
    float s0l, s0h, s1l, s1h;
    up2(s0l, s0h, s0); up2(s1l, s1h, s1);
    const float Sx = s0l + s1l;
    const float Sy = s0h + s1h;

    const ull xe0p = xq[0];
    const ull xe1p = xq[FH];
    const ull xT2p = xq[(TT - 2) * FH];
    const ull xT1p = xq[(TT - 1) * FH];
    float e0l, e0h, e1l, e1h, t2l, t2h, t1l, t1h;
    up2(e0l, e0h, xe0p); up2(e1l, e1h, xe1p);
    up2(t2l, t2h, xT2p); up2(t1l, t1h, xT1p);

    // analytic sum of conv over t (linear conv, SAME zero padding)
    const float wsum = w0 + w1 + w2 + w3 + w4;
    const float cT = (float)TT * bias;
    float scx, scy;
    {
        float sc = cT + wsum * Sx - w0 * (t2l + t1l) - w1 * t1l
                 - w3 * e0l - w4 * (e0l + e1l);
        scx = 1.0f + 0.5f / (1.0f + expf(-satt * sc * (1.0f / (float)TT)));
    }
    {
        float sc = cT + wsum * Sy - w0 * (t2h + t1h) - w1 * t1h
                 - w3 * e0h - w4 * (e0h + e1h);
        scy = 1.0f + 0.5f / (1.0f + expf(-satt * sc * (1.0f / (float)TT)));
    }

    // ---------- packed constants ----------
    const ull W0 = pk2(w0, w0), W1 = pk2(w1, w1), W2 = pk2(w2, w2);
    const ull W3 = pk2(w3, w3), W4 = pk2(w4, w4);
    const ull SC  = pk2(scx, scy);
    const ull Bp  = pk2(bias * scx, bias * scy);
    const ull DEC = pk2(0.9f, 0.9f);
    const float k3f = 0.1f / 3.0f;
    const ull K3   = pk2(k3f, k3f);
    const ull TH0C = pk2(0.1f * thr0, 0.1f * thr0);
    // atan degree-9 minimax coefficients, packed broadcast
    const ull A1 = pk2( 0.9998660f,  0.9998660f);
    const ull A3 = pk2(-0.3302995f, -0.3302995f);
    const ull A5 = pk2( 0.1801410f,  0.1801410f);
    const ull A7 = pk2(-0.0851330f, -0.0851330f);
    const ull A9 = pk2( 0.0208351f,  0.0208351f);
    const float qtr = 0.25f;

    // ---------- pass 2: fused conv + LIF, packed ----------
    // window: m2=x[t-2], m1=x[t-1], c0v=x[t], p1v=x[t+1]; cur{0,1} = x[t+2], x[t+3]
    ull m2 = 0ull, m1 = 0ull;
    ull c0v = xe0p, p1v = xe1p;
    ull cur0 = xq[2 * FH];
    ull cur1 = xq[3 * FH];

    ull mem = 0ull;
    ull thr = pk2(thr0, thr0);
    ull h1 = 0ull, h2 = 0ull;

    #define LIF_STEP(T_, PARITY_, PF_)                                          \
    {                                                                            \
        ull p2v = (PARITY_) ? cur1 : cur0;                                       \
        if (PF_) {                                                               \
            ull nv = __ldcs(&xq[((T_) + 4) * FH]);                               \
            if (PARITY_) cur1 = nv; else cur0 = nv;                              \
        }                                                                        \
        ull cv = mul2(W0, m2);                                                   \
        cv = fma2(W1, m1, cv);                                                   \
        cv = fma2(W2, c0v, cv);                                                  \
        cv = fma2(W3, p1v, cv);                                                  \
        cv = fma2(W4, p2v, cv);                                                  \
        ull xt = fma2(cv, SC, Bp);                                               \
        mem = fma2(DEC, mem, xt);                                                \
        ull dd = sub2(mem, thr);                                                 \
        float dl, dh; up2(dl, dh, dd);                                           \
        float al_ = fabsf(dl) * 1.5707964f;                                      \
        float ah_ = fabsf(dh) * 1.5707964f;                                      \
        float rl = __fdividef(1.0f, al_);                                        \
        float rh = __fdividef(1.0f, ah_);                                        \
        float tl = fminf(al_, rl);                                               \
        float th_ = fminf(ah_, rh);                                              \
        ull tk = pk2(tl, th_);                                                   \
        ull tt2 = mul2(tk, tk);                                                  \
        ull tt4 = mul2(tt2, tt2);                                                \
        ull e0_ = fma2(tt2, A3, A1);                                             \
        ull e1_ = fma2(tt2, A7, A5);                                             \
        e1_ = fma2(tt4, A9, e1_);                                                \
        ull pp = fma2(tt4, e1_, e0_);                                            \
        ull rr = mul2(tk, pp);                                                   \
        float prl, prh; up2(prl, prh, rr);                                       \
        float aal = (al_ > 1.0f) ? (1.5707964f - prl) : prl;                     \
        float aah = (ah_ > 1.0f) ? (1.5707964f - prh) : prh;                     \
        aal = copysignf(aal, dl);                                                \
        aah = copysignf(aah, dh);                                                \
        float sl = fmaf(aal, 0.15915494f, qtr);                                  \
        float sh = fmaf(aah, 0.15915494f, qtr);                                  \
        ull spike = pk2(sl, sh);                                                 \
        ull hs = add2(h1, h2);                                                   \
        hs = add2(hs, spike);                                                    \
        ull tmp = fma2(K3, hs, TH0C);                                            \
        thr = fma2(DEC, thr, tmp);                                               \
        ull st = mul2(spike, thr);                                               \
        mem = sub2(mem, st);                                                     \
        h1 = h2; h2 = spike;                                                     \
        __stcs(&oq[(T_) * FH], spike);                                           \
        m2 = m1; m1 = c0v; c0v = p1v; p1v = p2v;                                 \
    }

    // main chunks: t = 0 .. 123, prefetch t+4 valid (<= 127)
    #pragma unroll 1
    for (int c = 0; c < 31; ++c) {
        const int tb = c * 4;
        LIF_STEP(tb + 0, 0, true)
        LIF_STEP(tb + 1, 1, true)
        LIF_STEP(tb + 2, 0, true)
        LIF_STEP(tb + 3, 1, true)
    }
    // tail: t = 124..127. cur0=x[126], cur1=x[127] are consumed at t=124,125.
    LIF_STEP(124, 0, false)
    LIF_STEP(125, 1, false)
    // t=126,127 need x[128],x[129] = 0 (SAME zero padding) — zero the pipe.
    cur0 = 0ull;
    cur1 = 0ull;
    LIF_STEP(126, 0, false)
    LIF_STEP(127, 1, false)

    #undef LIF_STEP

    // mem output appended after spikes
    ((ull*)(out + (size_t)BB * TT * FF))[p] = mem;
}

extern "C" void kernel_launch(void* const* d_in, const int* in_sizes, int n_in,
                              void* d_out, int out_size)
{
    const float* x    = (const float*)d_in[0];
    const float* thr0 = (const float*)d_in[1];
    const float* cw   = (const float*)d_in[2];
    const float* cb   = (const float*)d_in[3];
    const float* sa   = (const float*)d_in[4];
    float* out = (float*)d_out;

    const int pairs = BB * FH;                 // 131072
    lif_fused_kernel<<<pairs / BLOCK, BLOCK>>>(x, thr0, cw, cb, sa, out);
}